// round 1
// baseline (speedup 1.0000x reference)
#include <cuda_runtime.h>
#include <math.h>
#include <float.h>

// Shapes (fixed for this problem)
#define SEQ   1024
#define DMODEL 1024
#define NHEAD 16
#define DHEAD 64
#define NBATCH 2
#define POS2  512   // 2*SPAN

// ---------------- scratch (device globals; no allocations allowed) ----------
__device__ float g_Q[NBATCH * SEQ * DMODEL];
__device__ float g_K[NBATCH * SEQ * DMODEL];
__device__ float g_V[NBATCH * SEQ * DMODEL];
__device__ float g_PQ[POS2 * DMODEL];
__device__ float g_PK[POS2 * DMODEL];
__device__ float g_c2p[NHEAD * NBATCH * SEQ * POS2];   // [h][b*S+q][p]
__device__ float g_p2c[NHEAD * NBATCH * SEQ * POS2];   // [h][b*S+k][p]
__device__ int   g_idxC[2047];
__device__ int   g_idxP[2047];

// ---------------- log-bucket (replicates JAX f32 op sequence) ---------------
__device__ __forceinline__ int log_bucket(int rel) {
    const int mid = 128;
    float absp;
    if (rel < mid && rel > -mid) absp = (float)(mid - 1);
    else absp = fabsf((float)rel);
    if (absp <= (float)mid) return rel;
    // np.log((512-1)/128) = 1.3843393291...
    float lp = ceilf(logf(absp / 128.0f) / 1.3843393291f * 127.0f) + 128.0f;
    float sgn = (rel > 0) ? 1.0f : ((rel < 0) ? -1.0f : 0.0f);
    return (int)(lp * sgn);
}

__global__ void init_tables_kernel() {
    int t = blockIdx.x * blockDim.x + threadIdx.x;
    if (t < 2047) {
        int delta = t - 1023;              // delta = q - k
        int bC = log_bucket(delta);
        g_idxC[t] = min(max(bC + 256, 0), 511);
        int bP = log_bucket(-delta);       // bucket(k - q)
        g_idxP[t] = min(max(-bP + 256, 0), 511);
    }
}

// ---------------- GEMM: C[M,1024] = A[M,1024] @ W[1024,1024] + bias ---------
// block tile 128(M) x 64(N), 256 threads, 8x4 register tile, K-chunk 16
__global__ __launch_bounds__(256) void gemm_bias_kernel(
    const float* __restrict__ A, const float* __restrict__ W,
    const float* __restrict__ bias, float* __restrict__ C) {
    __shared__ float As[16][132];   // [k][m], padded
    __shared__ float Bs[16][68];    // [k][n], padded

    int tid = threadIdx.x;
    int m0 = blockIdx.y * 128;
    int n0 = blockIdx.x * 64;
    int ty = tid >> 4, tx = tid & 15;

    int ar = tid >> 2;          // 0..63
    int ak = (tid & 3) * 4;     // 0,4,8,12
    int bk = tid >> 4;          // 0..15
    int bn = (tid & 15) * 4;    // 0..60

    float acc[8][4];
    #pragma unroll
    for (int i = 0; i < 8; i++)
        #pragma unroll
        for (int j = 0; j < 4; j++) acc[i][j] = 0.0f;

    for (int kk = 0; kk < 1024; kk += 16) {
        float4 a0 = *(const float4*)&A[(size_t)(m0 + ar) * 1024 + kk + ak];
        float4 a1 = *(const float4*)&A[(size_t)(m0 + ar + 64) * 1024 + kk + ak];
        float4 bv = *(const float4*)&W[(size_t)(kk + bk) * 1024 + n0 + bn];
        As[ak + 0][ar] = a0.x; As[ak + 1][ar] = a0.y;
        As[ak + 2][ar] = a0.z; As[ak + 3][ar] = a0.w;
        As[ak + 0][ar + 64] = a1.x; As[ak + 1][ar + 64] = a1.y;
        As[ak + 2][ar + 64] = a1.z; As[ak + 3][ar + 64] = a1.w;
        *(float4*)&Bs[bk][bn] = bv;
        __syncthreads();

        #pragma unroll
        for (int k = 0; k < 16; k++) {
            float4 x0 = *(float4*)&As[k][ty * 8];
            float4 x1 = *(float4*)&As[k][ty * 8 + 4];
            float4 y  = *(float4*)&Bs[k][tx * 4];
            float areg[8] = {x0.x, x0.y, x0.z, x0.w, x1.x, x1.y, x1.z, x1.w};
            float breg[4] = {y.x, y.y, y.z, y.w};
            #pragma unroll
            for (int i = 0; i < 8; i++)
                #pragma unroll
                for (int j = 0; j < 4; j++)
                    acc[i][j] = fmaf(areg[i], breg[j], acc[i][j]);
        }
        __syncthreads();
    }

    float4 bb = *(const float4*)&bias[n0 + tx * 4];
    #pragma unroll
    for (int i = 0; i < 8; i++) {
        float4 o;
        o.x = acc[i][0] + bb.x; o.y = acc[i][1] + bb.y;
        o.z = acc[i][2] + bb.z; o.w = acc[i][3] + bb.w;
        *(float4*)&C[(size_t)(m0 + ty * 8 + i) * 1024 + n0 + tx * 4] = o;
    }
}

// ------- per-head GEMM A@B^T over the head's 64-dim slice -------------------
// C[h][r][p] = sum_d A[r, h*64+d] * B[p, h*64+d];  tiles 64x64, 4x4 reg tile
__global__ __launch_bounds__(256) void gemm_abT_kernel(
    const float* __restrict__ A, const float* __restrict__ B,
    float* __restrict__ C, int M, int N) {
    __shared__ float At[64][68];   // [d][r]
    __shared__ float Bt[64][68];   // [d][p]

    int h  = blockIdx.z;
    int r0 = blockIdx.y * 64;
    int p0 = blockIdx.x * 64;
    int tid = threadIdx.x;
    int rr = tid >> 2;
    int d0 = (tid & 3) * 16;

    #pragma unroll
    for (int i = 0; i < 4; i++) {
        float4 va = *(const float4*)&A[(size_t)(r0 + rr) * 1024 + h * 64 + d0 + 4 * i];
        At[d0 + 4 * i + 0][rr] = va.x; At[d0 + 4 * i + 1][rr] = va.y;
        At[d0 + 4 * i + 2][rr] = va.z; At[d0 + 4 * i + 3][rr] = va.w;
        float4 vb = *(const float4*)&B[(size_t)(p0 + rr) * 1024 + h * 64 + d0 + 4 * i];
        Bt[d0 + 4 * i + 0][rr] = vb.x; Bt[d0 + 4 * i + 1][rr] = vb.y;
        Bt[d0 + 4 * i + 2][rr] = vb.z; Bt[d0 + 4 * i + 3][rr] = vb.w;
    }
    __syncthreads();

    int ty = tid >> 4, tx = tid & 15;
    float acc[4][4];
    #pragma unroll
    for (int i = 0; i < 4; i++)
        #pragma unroll
        for (int j = 0; j < 4; j++) acc[i][j] = 0.0f;

    #pragma unroll 8
    for (int d = 0; d < 64; d++) {
        float4 a = *(float4*)&At[d][ty * 4];
        float4 b = *(float4*)&Bt[d][tx * 4];
        float areg[4] = {a.x, a.y, a.z, a.w};
        float breg[4] = {b.x, b.y, b.z, b.w};
        #pragma unroll
        for (int i = 0; i < 4; i++)
            #pragma unroll
            for (int j = 0; j < 4; j++)
                acc[i][j] = fmaf(areg[i], breg[j], acc[i][j]);
    }

    #pragma unroll
    for (int i = 0; i < 4; i++) {
        float4 o; o.x = acc[i][0]; o.y = acc[i][1]; o.z = acc[i][2]; o.w = acc[i][3];
        *(float4*)&C[(size_t)h * M * N + (size_t)(r0 + ty * 4 + i) * N + p0 + tx * 4] = o;
    }
}

// ---------------- fused flash-style attention -------------------------------
// grid (S/64, B*H); 256 threads; 64 q-rows per CTA, k-tiles of 64
#define SMB (64 * 68)
__global__ __launch_bounds__(256) void attn_kernel(
    const int* __restrict__ mask, float* __restrict__ out) {
    extern __shared__ float sm[];
    float* Qt = sm;            // [d][q]
    float* Kt = sm + SMB;      // [d][k]
    float* Vs = sm + 2 * SMB;  // [k][d]
    float* Ps = sm + 3 * SMB;  // [k][q]

    int tid = threadIdx.x;
    int bh = blockIdx.y;
    int b = bh >> 4, h = bh & 15;
    int q0 = blockIdx.x * 64;
    int ty = tid >> 4, tx = tid & 15;
    int rr = tid >> 2, d0 = (tid & 3) * 16;

    // load Q tile transposed
    #pragma unroll
    for (int i = 0; i < 4; i++) {
        float4 v = *(const float4*)&g_Q[(size_t)(b * SEQ + q0 + rr) * 1024 + h * 64 + d0 + 4 * i];
        Qt[(d0 + 4 * i + 0) * 68 + rr] = v.x; Qt[(d0 + 4 * i + 1) * 68 + rr] = v.y;
        Qt[(d0 + 4 * i + 2) * 68 + rr] = v.z; Qt[(d0 + 4 * i + 3) * 68 + rr] = v.w;
    }

    float m_run[4], l_run[4], O[4][4];
    #pragma unroll
    for (int i = 0; i < 4; i++) {
        m_run[i] = -FLT_MAX; l_run[i] = 0.0f;
        #pragma unroll
        for (int j = 0; j < 4; j++) O[i][j] = 0.0f;
    }

    const float inv_scale = 0.07216878364870323f; // 1/sqrt(64*3)

    for (int k0 = 0; k0 < SEQ; k0 += 64) {
        __syncthreads();  // prev tile's Ps/Vs reads done; Qt visible after next sync
        #pragma unroll
        for (int i = 0; i < 4; i++) {
            float4 kv = *(const float4*)&g_K[(size_t)(b * SEQ + k0 + rr) * 1024 + h * 64 + d0 + 4 * i];
            Kt[(d0 + 4 * i + 0) * 68 + rr] = kv.x; Kt[(d0 + 4 * i + 1) * 68 + rr] = kv.y;
            Kt[(d0 + 4 * i + 2) * 68 + rr] = kv.z; Kt[(d0 + 4 * i + 3) * 68 + rr] = kv.w;
            float4 vv = *(const float4*)&g_V[(size_t)(b * SEQ + k0 + rr) * 1024 + h * 64 + d0 + 4 * i];
            *(float4*)&Vs[rr * 68 + d0 + 4 * i] = vv;
        }
        __syncthreads();

        // S = Q K^T  (4x4 register tile per thread)
        float s[4][4];
        #pragma unroll
        for (int i = 0; i < 4; i++)
            #pragma unroll
            for (int j = 0; j < 4; j++) s[i][j] = 0.0f;

        #pragma unroll 8
        for (int d = 0; d < 64; d++) {
            float4 a  = *(float4*)&Qt[d * 68 + ty * 4];
            float4 bb = *(float4*)&Kt[d * 68 + tx * 4];
            float areg[4] = {a.x, a.y, a.z, a.w};
            float breg[4] = {bb.x, bb.y, bb.z, bb.w};
            #pragma unroll
            for (int i = 0; i < 4; i++)
                #pragma unroll
                for (int j = 0; j < 4; j++)
                    s[i][j] = fmaf(areg[i], breg[j], s[i][j]);
        }

        // add disentangled bias, scale, mask
        #pragma unroll
        for (int i = 0; i < 4; i++) {
            int qg = q0 + ty * 4 + i;
            const float* c2prow = &g_c2p[((size_t)h * (NBATCH * SEQ) + b * SEQ + qg) * POS2];
            const int* mrow = &mask[((size_t)b * SEQ + qg) * SEQ];
            #pragma unroll
            for (int j = 0; j < 4; j++) {
                int kg = k0 + tx * 4 + j;
                int dlt = qg - kg + 1023;
                float c2p = c2prow[g_idxC[dlt]];
                float p2c = g_p2c[((size_t)h * (NBATCH * SEQ) + b * SEQ + kg) * POS2 + g_idxP[dlt]];
                float sc = (s[i][j] + c2p + p2c) * inv_scale;
                s[i][j] = mrow[kg] ? sc : -FLT_MAX;
            }
        }

        // online softmax update per q-row (row shared by 16 lanes of same ty)
        #pragma unroll
        for (int i = 0; i < 4; i++) {
            float mx = fmaxf(fmaxf(s[i][0], s[i][1]), fmaxf(s[i][2], s[i][3]));
            #pragma unroll
            for (int off = 1; off < 16; off <<= 1)
                mx = fmaxf(mx, __shfl_xor_sync(0xffffffffu, mx, off));
            float m_new = fmaxf(m_run[i], mx);
            float alpha = __expf(m_run[i] - m_new);
            float p[4], psum = 0.0f;
            #pragma unroll
            for (int j = 0; j < 4; j++) {
                p[j] = __expf(s[i][j] - m_new);
                psum += p[j];
            }
            #pragma unroll
            for (int off = 1; off < 16; off <<= 1)
                psum += __shfl_xor_sync(0xffffffffu, psum, off);
            l_run[i] = l_run[i] * alpha + psum;
            m_run[i] = m_new;
            #pragma unroll
            for (int j = 0; j < 4; j++) O[i][j] *= alpha;
            #pragma unroll
            for (int j = 0; j < 4; j++)
                Ps[(tx * 4 + j) * 68 + ty * 4 + i] = p[j];
        }
        __syncthreads();

        // O += P V
        #pragma unroll 8
        for (int k = 0; k < 64; k++) {
            float4 pp = *(float4*)&Ps[k * 68 + ty * 4];
            float4 vv = *(float4*)&Vs[k * 68 + tx * 4];
            float preg[4] = {pp.x, pp.y, pp.z, pp.w};
            float vreg[4] = {vv.x, vv.y, vv.z, vv.w};
            #pragma unroll
            for (int i = 0; i < 4; i++)
                #pragma unroll
                for (int j = 0; j < 4; j++)
                    O[i][j] = fmaf(preg[i], vreg[j], O[i][j]);
        }
    }

    // epilogue: divide by l; all-masked row -> 0 (matches reference zeroing)
    #pragma unroll
    for (int i = 0; i < 4; i++) {
        float invl = (m_run[i] == -FLT_MAX) ? 0.0f : (1.0f / l_run[i]);
        float4 o;
        o.x = O[i][0] * invl; o.y = O[i][1] * invl;
        o.z = O[i][2] * invl; o.w = O[i][3] * invl;
        *(float4*)&out[(size_t)(b * SEQ + q0 + ty * 4 + i) * 1024 + h * 64 + tx * 4] = o;
    }
}

// ---------------- launch ----------------------------------------------------
extern "C" void kernel_launch(void* const* d_in, const int* in_sizes, int n_in,
                              void* d_out, int out_size) {
    const float* hidden = (const float*)d_in[0];
    const int*   mask   = (const int*)d_in[1];
    const float* rel    = (const float*)d_in[2];
    const float* Wq     = (const float*)d_in[3];
    const float* bq     = (const float*)d_in[4];
    const float* Wk     = (const float*)d_in[5];
    const float* bk     = (const float*)d_in[6];
    const float* Wv     = (const float*)d_in[7];
    const float* bv     = (const float*)d_in[8];
    float* out = (float*)d_out;

    float *Q, *K, *V, *PQ, *PK, *C2P, *P2C;
    cudaGetSymbolAddress((void**)&Q,   g_Q);
    cudaGetSymbolAddress((void**)&K,   g_K);
    cudaGetSymbolAddress((void**)&V,   g_V);
    cudaGetSymbolAddress((void**)&PQ,  g_PQ);
    cudaGetSymbolAddress((void**)&PK,  g_PK);
    cudaGetSymbolAddress((void**)&C2P, g_c2p);
    cudaGetSymbolAddress((void**)&P2C, g_p2c);

    init_tables_kernel<<<8, 256>>>();

    // projections (M=2048) and positional projections (M=512)
    gemm_bias_kernel<<<dim3(16, 16), 256>>>(hidden, Wq, bq, Q);
    gemm_bias_kernel<<<dim3(16, 16), 256>>>(hidden, Wk, bk, K);
    gemm_bias_kernel<<<dim3(16, 16), 256>>>(hidden, Wv, bv, V);
    gemm_bias_kernel<<<dim3(16, 4),  256>>>(rel, Wq, bq, PQ);
    gemm_bias_kernel<<<dim3(16, 4),  256>>>(rel, Wk, bk, PK);

    // c2p_att = Q @ pos_k^T ; p2c_att = K @ pos_q^T (per head)
    gemm_abT_kernel<<<dim3(8, 32, 16), 256>>>(Q, PK, C2P, NBATCH * SEQ, POS2);
    gemm_abT_kernel<<<dim3(8, 32, 16), 256>>>(K, PQ, P2C, NBATCH * SEQ, POS2);

    // fused attention
    int smem = 4 * SMB * (int)sizeof(float);
    cudaFuncSetAttribute(attn_kernel, cudaFuncAttributeMaxDynamicSharedMemorySize, smem);
    attn_kernel<<<dim3(SEQ / 64, NBATCH * NHEAD), 256, smem>>>(mask, out);
}

// round 2
// speedup vs baseline: 1.7104x; 1.7104x over previous
#include <cuda_runtime.h>
#include <math.h>
#include <float.h>
#include <stdint.h>

// Shapes (fixed for this problem)
#define SEQ    1024
#define DMODEL 1024
#define NHEAD  16
#define DHEAD  64
#define NBATCH 2
#define POS2   512   // 2*SPAN

// ---------------- scratch (device globals; no allocations allowed) ----------
__device__ float g_Q[NBATCH * SEQ * DMODEL];
__device__ float g_K[NBATCH * SEQ * DMODEL];
__device__ float g_V[NBATCH * SEQ * DMODEL];
__device__ float g_PQ[POS2 * DMODEL];
__device__ float g_PK[POS2 * DMODEL];
__device__ float g_c2p[NHEAD * NBATCH * SEQ * POS2];   // [h][b*S+q][p]
__device__ float g_p2c[NHEAD * NBATCH * SEQ * POS2];   // [h][b*S+k][p]
__device__ int   g_idxC[2047];
__device__ int   g_idxP[2047];

// ---------------- helpers ----------------------------------------------------
__device__ __forceinline__ uint32_t f2tf32(float x) {
    uint32_t r;
    asm("cvt.rna.tf32.f32 %0, %1;" : "=r"(r) : "f"(x));
    return r;
}

__device__ __forceinline__ void mma_tf32(float c[4], const uint32_t a[4], const uint32_t b[2]) {
    asm volatile(
        "mma.sync.aligned.m16n8k8.row.col.f32.tf32.tf32.f32 "
        "{%0,%1,%2,%3}, {%4,%5,%6,%7}, {%8,%9}, {%0,%1,%2,%3};"
        : "+f"(c[0]), "+f"(c[1]), "+f"(c[2]), "+f"(c[3])
        : "r"(a[0]), "r"(a[1]), "r"(a[2]), "r"(a[3]), "r"(b[0]), "r"(b[1]));
}

// ---------------- log-bucket (replicates JAX f32 op sequence) ---------------
__device__ __forceinline__ int log_bucket(int rel) {
    const int mid = 128;
    float absp;
    if (rel < mid && rel > -mid) absp = (float)(mid - 1);
    else absp = fabsf((float)rel);
    if (absp <= (float)mid) return rel;
    float lp = ceilf(logf(absp / 128.0f) / 1.3843393291f * 127.0f) + 128.0f;
    float sgn = (rel > 0) ? 1.0f : ((rel < 0) ? -1.0f : 0.0f);
    return (int)(lp * sgn);
}

__global__ void init_tables_kernel() {
    int t = blockIdx.x * blockDim.x + threadIdx.x;
    if (t < 2047) {
        int delta = t - 1023;
        int bC = log_bucket(delta);
        g_idxC[t] = min(max(bC + 256, 0), 511);
        int bP = log_bucket(-delta);
        g_idxP[t] = min(max(-bP + 256, 0), 511);
    }
}

// ================= TF32 GEMM: C = A[M,1024] @ W[1024,1024] + bias ============
// 128x128 tile, K-step 32, 256 threads (8 warps: 2m x 4n), reg-staged double buffer.
// blockIdx.z selects which (W, bias, C) triple.
#define QKV_AS_STRIDE 36
#define QKV_BS_STRIDE 136
#define QKV_ABUF (128 * QKV_AS_STRIDE)
#define QKV_BBUF (32 * QKV_BS_STRIDE)

__global__ __launch_bounds__(256) void gemm_qkv_tf32(
    const float* __restrict__ A,
    const float* __restrict__ W0, const float* __restrict__ W1, const float* __restrict__ W2,
    const float* __restrict__ b0, const float* __restrict__ b1, const float* __restrict__ b2,
    float* __restrict__ C0, float* __restrict__ C1, float* __restrict__ C2) {

    int z = blockIdx.z;
    const float* W = (z == 0) ? W0 : (z == 1) ? W1 : W2;
    const float* bias = (z == 0) ? b0 : (z == 1) ? b1 : b2;
    float* C = (z == 0) ? C0 : (z == 1) ? C1 : C2;

    extern __shared__ uint32_t smu[];
    uint32_t* As = smu;                 // [2][128][36]
    uint32_t* Bs = smu + 2 * QKV_ABUF;  // [2][32][136]

    int tid = threadIdx.x;
    int lane = tid & 31, wid = tid >> 5;
    int wm = (wid >> 2) * 64, wn = (wid & 3) * 32;
    int m0 = blockIdx.y * 128, n0 = blockIdx.x * 128;

    int arow = tid >> 3, acol = (tid & 7) * 4;     // A: 32 rows/pass, 4 passes
    int brow = tid >> 5, bcol = (tid & 31) * 4;    // B: 8 rows/pass, 4 passes

    float4 ra[4], rb[4];

    float acc[16][4];
    #pragma unroll
    for (int t = 0; t < 16; t++)
        #pragma unroll
        for (int j = 0; j < 4; j++) acc[t][j] = 0.0f;

    // ---- load tile 0 into regs, store to buf 0
    #pragma unroll
    for (int p = 0; p < 4; p++) {
        ra[p] = *(const float4*)&A[(size_t)(m0 + arow + p * 32) * 1024 + acol];
        rb[p] = *(const float4*)&W[(size_t)(brow + p * 8) * 1024 + n0 + bcol];
    }
    #pragma unroll
    for (int p = 0; p < 4; p++) {
        uint32_t* d = &As[(arow + p * 32) * QKV_AS_STRIDE + acol];
        d[0] = f2tf32(ra[p].x); d[1] = f2tf32(ra[p].y); d[2] = f2tf32(ra[p].z); d[3] = f2tf32(ra[p].w);
        uint32_t* e = &Bs[(brow + p * 8) * QKV_BS_STRIDE + bcol];
        e[0] = f2tf32(rb[p].x); e[1] = f2tf32(rb[p].y); e[2] = f2tf32(rb[p].z); e[3] = f2tf32(rb[p].w);
    }
    __syncthreads();

    int buf = 0;
    for (int kk = 32; kk <= 1024; kk += 32) {
        // prefetch next tile
        if (kk < 1024) {
            #pragma unroll
            for (int p = 0; p < 4; p++) {
                ra[p] = *(const float4*)&A[(size_t)(m0 + arow + p * 32) * 1024 + kk + acol];
                rb[p] = *(const float4*)&W[(size_t)(kk + brow + p * 8) * 1024 + n0 + bcol];
            }
        }
        // compute current buf
        const uint32_t* Ab = &As[buf * QKV_ABUF];
        const uint32_t* Bb = &Bs[buf * QKV_BBUF];
        #pragma unroll
        for (int ks = 0; ks < 4; ks++) {
            int kb = ks * 8;
            uint32_t af[4][4], bf[4][2];
            #pragma unroll
            for (int i = 0; i < 4; i++) {
                int r = wm + i * 16 + (lane >> 2);
                int c = kb + (lane & 3);
                af[i][0] = Ab[r * QKV_AS_STRIDE + c];
                af[i][1] = Ab[(r + 8) * QKV_AS_STRIDE + c];
                af[i][2] = Ab[r * QKV_AS_STRIDE + c + 4];
                af[i][3] = Ab[(r + 8) * QKV_AS_STRIDE + c + 4];
            }
            #pragma unroll
            for (int j = 0; j < 4; j++) {
                int r = kb + (lane & 3);
                int c = wn + j * 8 + (lane >> 2);
                bf[j][0] = Bb[r * QKV_BS_STRIDE + c];
                bf[j][1] = Bb[(r + 4) * QKV_BS_STRIDE + c];
            }
            #pragma unroll
            for (int i = 0; i < 4; i++)
                #pragma unroll
                for (int j = 0; j < 4; j++)
                    mma_tf32(acc[i * 4 + j], af[i], bf[j]);
        }
        __syncthreads();
        if (kk < 1024) {
            buf ^= 1;
            #pragma unroll
            for (int p = 0; p < 4; p++) {
                uint32_t* d = &As[buf * QKV_ABUF + (arow + p * 32) * QKV_AS_STRIDE + acol];
                d[0] = f2tf32(ra[p].x); d[1] = f2tf32(ra[p].y); d[2] = f2tf32(ra[p].z); d[3] = f2tf32(ra[p].w);
                uint32_t* e = &Bs[buf * QKV_BBUF + (brow + p * 8) * QKV_BS_STRIDE + bcol];
                e[0] = f2tf32(rb[p].x); e[1] = f2tf32(rb[p].y); e[2] = f2tf32(rb[p].z); e[3] = f2tf32(rb[p].w);
            }
            __syncthreads();
        }
    }

    // epilogue
    #pragma unroll
    for (int i = 0; i < 4; i++) {
        #pragma unroll
        for (int j = 0; j < 4; j++) {
            int r = m0 + wm + i * 16 + (lane >> 2);
            int c = n0 + wn + j * 8 + (lane & 3) * 2;
            float bx = bias[c], by = bias[c + 1];
            float* cp = &C[(size_t)r * 1024 + c];
            float2 v0 = {acc[i * 4 + j][0] + bx, acc[i * 4 + j][1] + by};
            *(float2*)cp = v0;
            float2 v1 = {acc[i * 4 + j][2] + bx, acc[i * 4 + j][3] + by};
            *(float2*)&C[(size_t)(r + 8) * 1024 + c] = v1;
        }
    }
}

// ============ TF32 per-head A@B^T: C[z][r][p], K=64 ==========================
// tile 128(r) x 64(p), 256 threads (8 warps: 4m x 2n), single K load.
// z = blockIdx.z: z<16 -> c2p (A=Q,B=PK), else p2c (A=K,B=PQ); h=z&15.
#define ABT_AS_STRIDE 68
#define ABT_BS_STRIDE 136

__global__ __launch_bounds__(256) void gemm_abT_tf32() {
    int z = blockIdx.z;
    int h = z & 15;
    const float* Ap = (z < 16) ? g_Q : g_K;
    const float* Bp = (z < 16) ? g_PK : g_PQ;
    float* Cp = (z < 16) ? g_c2p : g_p2c;

    extern __shared__ uint32_t smu[];
    uint32_t* As = smu;                       // [128][68]
    uint32_t* Bs = smu + 128 * ABT_AS_STRIDE; // [64][136]  ([d][p])

    int tid = threadIdx.x;
    int lane = tid & 31, wid = tid >> 5;
    int wm = (wid >> 1) * 32, wn = (wid & 1) * 32;
    int r0 = blockIdx.y * 128, p0 = blockIdx.x * 64;

    // load A tile [128][64]
    {
        int row = tid >> 4, col = (tid & 15) * 4;
        #pragma unroll
        for (int p = 0; p < 8; p++) {
            float4 v = *(const float4*)&Ap[(size_t)(r0 + row + p * 16) * 1024 + h * 64 + col];
            uint32_t* d = &As[(row + p * 16) * ABT_AS_STRIDE + col];
            d[0] = f2tf32(v.x); d[1] = f2tf32(v.y); d[2] = f2tf32(v.z); d[3] = f2tf32(v.w);
        }
    }
    // load B tile transposed: Bs[d][p]
    {
        int pp = tid & 63, d4 = (tid >> 6) * 4;
        #pragma unroll
        for (int ps = 0; ps < 4; ps++) {
            int d = d4 + ps * 16;
            float4 v = *(const float4*)&Bp[(size_t)(p0 + pp) * 1024 + h * 64 + d];
            Bs[(d + 0) * ABT_BS_STRIDE + pp] = f2tf32(v.x);
            Bs[(d + 1) * ABT_BS_STRIDE + pp] = f2tf32(v.y);
            Bs[(d + 2) * ABT_BS_STRIDE + pp] = f2tf32(v.z);
            Bs[(d + 3) * ABT_BS_STRIDE + pp] = f2tf32(v.w);
        }
    }
    __syncthreads();

    float acc[8][4];
    #pragma unroll
    for (int t = 0; t < 8; t++)
        #pragma unroll
        for (int j = 0; j < 4; j++) acc[t][j] = 0.0f;

    #pragma unroll
    for (int ks = 0; ks < 8; ks++) {
        int kb = ks * 8;
        uint32_t af[2][4], bf[4][2];
        #pragma unroll
        for (int i = 0; i < 2; i++) {
            int r = wm + i * 16 + (lane >> 2);
            int c = kb + (lane & 3);
            af[i][0] = As[r * ABT_AS_STRIDE + c];
            af[i][1] = As[(r + 8) * ABT_AS_STRIDE + c];
            af[i][2] = As[r * ABT_AS_STRIDE + c + 4];
            af[i][3] = As[(r + 8) * ABT_AS_STRIDE + c + 4];
        }
        #pragma unroll
        for (int j = 0; j < 4; j++) {
            int r = kb + (lane & 3);
            int c = wn + j * 8 + (lane >> 2);
            bf[j][0] = Bs[r * ABT_BS_STRIDE + c];
            bf[j][1] = Bs[(r + 4) * ABT_BS_STRIDE + c];
        }
        #pragma unroll
        for (int i = 0; i < 2; i++)
            #pragma unroll
            for (int j = 0; j < 4; j++)
                mma_tf32(acc[i * 4 + j], af[i], bf[j]);
    }

    #pragma unroll
    for (int i = 0; i < 2; i++) {
        #pragma unroll
        for (int j = 0; j < 4; j++) {
            int r = r0 + wm + i * 16 + (lane >> 2);
            int c = p0 + wn + j * 8 + (lane & 3) * 2;
            float* cp = &Cp[((size_t)h * (NBATCH * SEQ) + r) * POS2 + c];
            float2 v0 = {acc[i * 4 + j][0], acc[i * 4 + j][1]};
            *(float2*)cp = v0;
            float2 v1 = {acc[i * 4 + j][2], acc[i * 4 + j][3]};
            *(float2*)&Cp[((size_t)h * (NBATCH * SEQ) + r + 8) * POS2 + c] = v1;
        }
    }
}

// ---------------- fused flash-style attention (fp32) -------------------------
#define SMB (64 * 68)
__global__ __launch_bounds__(256) void attn_kernel(
    const int* __restrict__ mask, float* __restrict__ out) {
    extern __shared__ float sm[];
    float* Qt = sm;            // [d][q]
    float* Kt = sm + SMB;      // [d][k]
    float* Vs = sm + 2 * SMB;  // [k][d]
    float* Ps = sm + 3 * SMB;  // [k][q]

    int tid = threadIdx.x;
    int bh = blockIdx.y;
    int b = bh >> 4, h = bh & 15;
    int q0 = blockIdx.x * 64;
    int ty = tid >> 4, tx = tid & 15;
    int rr = tid >> 2, d0 = (tid & 3) * 16;

    #pragma unroll
    for (int i = 0; i < 4; i++) {
        float4 v = *(const float4*)&g_Q[(size_t)(b * SEQ + q0 + rr) * 1024 + h * 64 + d0 + 4 * i];
        Qt[(d0 + 4 * i + 0) * 68 + rr] = v.x; Qt[(d0 + 4 * i + 1) * 68 + rr] = v.y;
        Qt[(d0 + 4 * i + 2) * 68 + rr] = v.z; Qt[(d0 + 4 * i + 3) * 68 + rr] = v.w;
    }

    float m_run[4], l_run[4], O[4][4];
    #pragma unroll
    for (int i = 0; i < 4; i++) {
        m_run[i] = -FLT_MAX; l_run[i] = 0.0f;
        #pragma unroll
        for (int j = 0; j < 4; j++) O[i][j] = 0.0f;
    }

    const float inv_scale = 0.07216878364870323f; // 1/sqrt(64*3)

    for (int k0 = 0; k0 < SEQ; k0 += 64) {
        __syncthreads();
        #pragma unroll
        for (int i = 0; i < 4; i++) {
            float4 kv = *(const float4*)&g_K[(size_t)(b * SEQ + k0 + rr) * 1024 + h * 64 + d0 + 4 * i];
            Kt[(d0 + 4 * i + 0) * 68 + rr] = kv.x; Kt[(d0 + 4 * i + 1) * 68 + rr] = kv.y;
            Kt[(d0 + 4 * i + 2) * 68 + rr] = kv.z; Kt[(d0 + 4 * i + 3) * 68 + rr] = kv.w;
            float4 vv = *(const float4*)&g_V[(size_t)(b * SEQ + k0 + rr) * 1024 + h * 64 + d0 + 4 * i];
            *(float4*)&Vs[rr * 68 + d0 + 4 * i] = vv;
        }
        __syncthreads();

        float s[4][4];
        #pragma unroll
        for (int i = 0; i < 4; i++)
            #pragma unroll
            for (int j = 0; j < 4; j++) s[i][j] = 0.0f;

        #pragma unroll 8
        for (int d = 0; d < 64; d++) {
            float4 a  = *(float4*)&Qt[d * 68 + ty * 4];
            float4 bb = *(float4*)&Kt[d * 68 + tx * 4];
            float areg[4] = {a.x, a.y, a.z, a.w};
            float breg[4] = {bb.x, bb.y, bb.z, bb.w};
            #pragma unroll
            for (int i = 0; i < 4; i++)
                #pragma unroll
                for (int j = 0; j < 4; j++)
                    s[i][j] = fmaf(areg[i], breg[j], s[i][j]);
        }

        #pragma unroll
        for (int i = 0; i < 4; i++) {
            int qg = q0 + ty * 4 + i;
            const float* c2prow = &g_c2p[((size_t)h * (NBATCH * SEQ) + b * SEQ + qg) * POS2];
            const int* mrow = &mask[((size_t)b * SEQ + qg) * SEQ];
            #pragma unroll
            for (int j = 0; j < 4; j++) {
                int kg = k0 + tx * 4 + j;
                int dlt = qg - kg + 1023;
                float c2p = c2prow[g_idxC[dlt]];
                float p2c = g_p2c[((size_t)h * (NBATCH * SEQ) + b * SEQ + kg) * POS2 + g_idxP[dlt]];
                float sc = (s[i][j] + c2p + p2c) * inv_scale;
                s[i][j] = mrow[kg] ? sc : -FLT_MAX;
            }
        }

        #pragma unroll
        for (int i = 0; i < 4; i++) {
            float mx = fmaxf(fmaxf(s[i][0], s[i][1]), fmaxf(s[i][2], s[i][3]));
            #pragma unroll
            for (int off = 1; off < 16; off <<= 1)
                mx = fmaxf(mx, __shfl_xor_sync(0xffffffffu, mx, off));
            float m_new = fmaxf(m_run[i], mx);
            float alpha = __expf(m_run[i] - m_new);
            float p[4], psum = 0.0f;
            #pragma unroll
            for (int j = 0; j < 4; j++) {
                p[j] = __expf(s[i][j] - m_new);
                psum += p[j];
            }
            #pragma unroll
            for (int off = 1; off < 16; off <<= 1)
                psum += __shfl_xor_sync(0xffffffffu, psum, off);
            l_run[i] = l_run[i] * alpha + psum;
            m_run[i] = m_new;
            #pragma unroll
            for (int j = 0; j < 4; j++) O[i][j] *= alpha;
            #pragma unroll
            for (int j = 0; j < 4; j++)
                Ps[(tx * 4 + j) * 68 + ty * 4 + i] = p[j];
        }
        __syncthreads();

        #pragma unroll 8
        for (int k = 0; k < 64; k++) {
            float4 pp = *(float4*)&Ps[k * 68 + ty * 4];
            float4 vv = *(float4*)&Vs[k * 68 + tx * 4];
            float preg[4] = {pp.x, pp.y, pp.z, pp.w};
            float vreg[4] = {vv.x, vv.y, vv.z, vv.w};
            #pragma unroll
            for (int i = 0; i < 4; i++)
                #pragma unroll
                for (int j = 0; j < 4; j++)
                    O[i][j] = fmaf(preg[i], vreg[j], O[i][j]);
        }
    }

    #pragma unroll
    for (int i = 0; i < 4; i++) {
        float invl = (m_run[i] == -FLT_MAX) ? 0.0f : (1.0f / l_run[i]);
        float4 o;
        o.x = O[i][0] * invl; o.y = O[i][1] * invl;
        o.z = O[i][2] * invl; o.w = O[i][3] * invl;
        *(float4*)&out[(size_t)(b * SEQ + q0 + ty * 4 + i) * 1024 + h * 64 + tx * 4] = o;
    }
}

// ---------------- launch ----------------------------------------------------
extern "C" void kernel_launch(void* const* d_in, const int* in_sizes, int n_in,
                              void* d_out, int out_size) {
    const float* hidden = (const float*)d_in[0];
    const int*   mask   = (const int*)d_in[1];
    const float* rel    = (const float*)d_in[2];
    const float* Wq     = (const float*)d_in[3];
    const float* bq     = (const float*)d_in[4];
    const float* Wk     = (const float*)d_in[5];
    const float* bk     = (const float*)d_in[6];
    const float* Wv     = (const float*)d_in[7];
    const float* bv     = (const float*)d_in[8];
    float* out = (float*)d_out;

    float *Q, *K, *V, *PQ, *PK;
    cudaGetSymbolAddress((void**)&Q,  g_Q);
    cudaGetSymbolAddress((void**)&K,  g_K);
    cudaGetSymbolAddress((void**)&V,  g_V);
    cudaGetSymbolAddress((void**)&PQ, g_PQ);
    cudaGetSymbolAddress((void**)&PK, g_PK);

    init_tables_kernel<<<8, 256>>>();

    int smem_qkv = (2 * QKV_ABUF + 2 * QKV_BBUF) * (int)sizeof(uint32_t);
    cudaFuncSetAttribute(gemm_qkv_tf32, cudaFuncAttributeMaxDynamicSharedMemorySize, smem_qkv);
    // Q/K/V projections: M=2048
    gemm_qkv_tf32<<<dim3(8, 16, 3), 256, smem_qkv>>>(
        hidden, Wq, Wk, Wv, bq, bk, bv, Q, K, V);
    // positional projections: M=512 (z in {0,1} -> PQ, PK)
    gemm_qkv_tf32<<<dim3(8, 4, 2), 256, smem_qkv>>>(
        rel, Wq, Wk, Wk, bq, bk, bk, PQ, PK, PK);

    int smem_abt = (128 * ABT_AS_STRIDE + 64 * ABT_BS_STRIDE) * (int)sizeof(uint32_t);
    cudaFuncSetAttribute(gemm_abT_tf32, cudaFuncAttributeMaxDynamicSharedMemorySize, smem_abt);
    gemm_abT_tf32<<<dim3(8, 16, 32), 256, smem_abt>>>();

    int smem_attn = 4 * SMB * (int)sizeof(float);
    cudaFuncSetAttribute(attn_kernel, cudaFuncAttributeMaxDynamicSharedMemorySize, smem_attn);
    attn_kernel<<<dim3(SEQ / 64, NBATCH * NHEAD), 256, smem_attn>>>(mask, out);
}

// round 3
// speedup vs baseline: 2.4897x; 1.4557x over previous
#include <cuda_runtime.h>
#include <math.h>
#include <float.h>
#include <stdint.h>

#define SEQ    1024
#define DMODEL 1024
#define NHEAD  16
#define DHEAD  64
#define NBATCH 2
#define POS2   512

// ---------------- scratch ----------------------------------------------------
__device__ float g_Q[NBATCH * SEQ * DMODEL];
__device__ float g_K[NBATCH * SEQ * DMODEL];
__device__ float g_V[NBATCH * SEQ * DMODEL];
__device__ float g_PQ[POS2 * DMODEL];
__device__ float g_PK[POS2 * DMODEL];
__device__ float g_c2p[NHEAD * NBATCH * SEQ * POS2];
__device__ float g_p2c[NHEAD * NBATCH * SEQ * POS2];
__device__ int   g_idxC[2047];
__device__ int   g_idxP[2047];

// ---------------- helpers ----------------------------------------------------
__device__ __forceinline__ uint32_t f2tf32(float x) {
    uint32_t r;
    asm("cvt.rna.tf32.f32 %0, %1;" : "=r"(r) : "f"(x));
    return r;
}
__device__ __forceinline__ void mma_tf32(float c[4], const uint32_t a[4], const uint32_t b[2]) {
    asm volatile(
        "mma.sync.aligned.m16n8k8.row.col.f32.tf32.tf32.f32 "
        "{%0,%1,%2,%3}, {%4,%5,%6,%7}, {%8,%9}, {%0,%1,%2,%3};"
        : "+f"(c[0]), "+f"(c[1]), "+f"(c[2]), "+f"(c[3])
        : "r"(a[0]), "r"(a[1]), "r"(a[2]), "r"(a[3]), "r"(b[0]), "r"(b[1]));
}

// ---------------- log-bucket tables ------------------------------------------
__device__ __forceinline__ int log_bucket(int rel) {
    const int mid = 128;
    float absp;
    if (rel < mid && rel > -mid) absp = (float)(mid - 1);
    else absp = fabsf((float)rel);
    if (absp <= (float)mid) return rel;
    float lp = ceilf(logf(absp / 128.0f) / 1.3843393291f * 127.0f) + 128.0f;
    float sgn = (rel > 0) ? 1.0f : ((rel < 0) ? -1.0f : 0.0f);
    return (int)(lp * sgn);
}
__global__ void init_tables_kernel() {
    int t = blockIdx.x * blockDim.x + threadIdx.x;
    if (t < 2047) {
        int delta = t - 1023;
        int bC = log_bucket(delta);
        g_idxC[t] = min(max(bC + 256, 0), 511);
        int bP = log_bucket(-delta);
        g_idxP[t] = min(max(-bP + 256, 0), 511);
    }
}

// ================= TF32 GEMM: projections (QKV + positional merged) ==========
// 128x128 tile, K-step 32, 256 threads; y<16: hidden->Q/K/V, y>=16: rel->PQ/PK
#define QKV_AS_STRIDE 36
#define QKV_BS_STRIDE 136
#define QKV_ABUF (128 * QKV_AS_STRIDE)
#define QKV_BBUF (32 * QKV_BS_STRIDE)

__global__ __launch_bounds__(256) void gemm_proj_tf32(
    const float* __restrict__ hidden, const float* __restrict__ rel,
    const float* __restrict__ Wq, const float* __restrict__ Wk, const float* __restrict__ Wv,
    const float* __restrict__ bq, const float* __restrict__ bk, const float* __restrict__ bv) {

    int z = blockIdx.z;
    int y = blockIdx.y;
    const float* A;
    float* C;
    int m0;
    if (y < 16) {
        A = hidden; m0 = y * 128;
        C = (z == 0) ? g_Q : (z == 1) ? g_K : g_V;
    } else {
        if (z == 2) return;
        A = rel; m0 = (y - 16) * 128;
        C = (z == 0) ? g_PQ : g_PK;
    }
    const float* W = (z == 0) ? Wq : (z == 1) ? Wk : Wv;
    const float* bias = (z == 0) ? bq : (z == 1) ? bk : bv;

    extern __shared__ uint32_t smu[];
    uint32_t* As = smu;
    uint32_t* Bs = smu + 2 * QKV_ABUF;

    int tid = threadIdx.x;
    int lane = tid & 31, wid = tid >> 5;
    int wm = (wid >> 2) * 64, wn = (wid & 3) * 32;
    int n0 = blockIdx.x * 128;

    int arow = tid >> 3, acol = (tid & 7) * 4;
    int brow = tid >> 5, bcol = (tid & 31) * 4;

    float4 ra[4], rb[4];
    float acc[16][4];
    #pragma unroll
    for (int t = 0; t < 16; t++)
        #pragma unroll
        for (int j = 0; j < 4; j++) acc[t][j] = 0.0f;

    #pragma unroll
    for (int p = 0; p < 4; p++) {
        ra[p] = *(const float4*)&A[(size_t)(m0 + arow + p * 32) * 1024 + acol];
        rb[p] = *(const float4*)&W[(size_t)(brow + p * 8) * 1024 + n0 + bcol];
    }
    #pragma unroll
    for (int p = 0; p < 4; p++) {
        uint32_t* d = &As[(arow + p * 32) * QKV_AS_STRIDE + acol];
        d[0] = f2tf32(ra[p].x); d[1] = f2tf32(ra[p].y); d[2] = f2tf32(ra[p].z); d[3] = f2tf32(ra[p].w);
        uint32_t* e = &Bs[(brow + p * 8) * QKV_BS_STRIDE + bcol];
        e[0] = f2tf32(rb[p].x); e[1] = f2tf32(rb[p].y); e[2] = f2tf32(rb[p].z); e[3] = f2tf32(rb[p].w);
    }
    __syncthreads();

    int buf = 0;
    for (int kk = 32; kk <= 1024; kk += 32) {
        if (kk < 1024) {
            #pragma unroll
            for (int p = 0; p < 4; p++) {
                ra[p] = *(const float4*)&A[(size_t)(m0 + arow + p * 32) * 1024 + kk + acol];
                rb[p] = *(const float4*)&W[(size_t)(kk + brow + p * 8) * 1024 + n0 + bcol];
            }
        }
        const uint32_t* Ab = &As[buf * QKV_ABUF];
        const uint32_t* Bb = &Bs[buf * QKV_BBUF];
        #pragma unroll
        for (int ks = 0; ks < 4; ks++) {
            int kb = ks * 8;
            uint32_t af[4][4], bf[4][2];
            #pragma unroll
            for (int i = 0; i < 4; i++) {
                int r = wm + i * 16 + (lane >> 2);
                int c = kb + (lane & 3);
                af[i][0] = Ab[r * QKV_AS_STRIDE + c];
                af[i][1] = Ab[(r + 8) * QKV_AS_STRIDE + c];
                af[i][2] = Ab[r * QKV_AS_STRIDE + c + 4];
                af[i][3] = Ab[(r + 8) * QKV_AS_STRIDE + c + 4];
            }
            #pragma unroll
            for (int j = 0; j < 4; j++) {
                int r = kb + (lane & 3);
                int c = wn + j * 8 + (lane >> 2);
                bf[j][0] = Bb[r * QKV_BS_STRIDE + c];
                bf[j][1] = Bb[(r + 4) * QKV_BS_STRIDE + c];
            }
            #pragma unroll
            for (int i = 0; i < 4; i++)
                #pragma unroll
                for (int j = 0; j < 4; j++)
                    mma_tf32(acc[i * 4 + j], af[i], bf[j]);
        }
        __syncthreads();
        if (kk < 1024) {
            buf ^= 1;
            #pragma unroll
            for (int p = 0; p < 4; p++) {
                uint32_t* d = &As[buf * QKV_ABUF + (arow + p * 32) * QKV_AS_STRIDE + acol];
                d[0] = f2tf32(ra[p].x); d[1] = f2tf32(ra[p].y); d[2] = f2tf32(ra[p].z); d[3] = f2tf32(ra[p].w);
                uint32_t* e = &Bs[buf * QKV_BBUF + (brow + p * 8) * QKV_BS_STRIDE + bcol];
                e[0] = f2tf32(rb[p].x); e[1] = f2tf32(rb[p].y); e[2] = f2tf32(rb[p].z); e[3] = f2tf32(rb[p].w);
            }
            __syncthreads();
        }
    }

    #pragma unroll
    for (int i = 0; i < 4; i++) {
        #pragma unroll
        for (int j = 0; j < 4; j++) {
            int r = m0 + wm + i * 16 + (lane >> 2);
            int c = n0 + wn + j * 8 + (lane & 3) * 2;
            float bx = bias[c], by = bias[c + 1];
            float2 v0 = {acc[i * 4 + j][0] + bx, acc[i * 4 + j][1] + by};
            *(float2*)&C[(size_t)r * 1024 + c] = v0;
            float2 v1 = {acc[i * 4 + j][2] + bx, acc[i * 4 + j][3] + by};
            *(float2*)&C[(size_t)(r + 8) * 1024 + c] = v1;
        }
    }
}

// ============ TF32 per-head A@B^T (c2p_att / p2c_att) ========================
#define ABT_AS_STRIDE 68
#define ABT_BS_STRIDE 136

__global__ __launch_bounds__(256) void gemm_abT_tf32() {
    int z = blockIdx.z;
    int h = z & 15;
    const float* Ap = (z < 16) ? g_Q : g_K;
    const float* Bp = (z < 16) ? g_PK : g_PQ;
    float* Cp = (z < 16) ? g_c2p : g_p2c;

    extern __shared__ uint32_t smu[];
    uint32_t* As = smu;                       // [128][68]
    uint32_t* Bs = smu + 128 * ABT_AS_STRIDE; // [64][136]

    int tid = threadIdx.x;
    int lane = tid & 31, wid = tid >> 5;
    int wm = (wid >> 1) * 32, wn = (wid & 1) * 32;
    int r0 = blockIdx.y * 128, p0 = blockIdx.x * 64;

    {
        int row = tid >> 4, col = (tid & 15) * 4;
        #pragma unroll
        for (int p = 0; p < 8; p++) {
            float4 v = *(const float4*)&Ap[(size_t)(r0 + row + p * 16) * 1024 + h * 64 + col];
            uint32_t* d = &As[(row + p * 16) * ABT_AS_STRIDE + col];
            d[0] = f2tf32(v.x); d[1] = f2tf32(v.y); d[2] = f2tf32(v.z); d[3] = f2tf32(v.w);
        }
    }
    {
        int pp = tid & 63, d4 = (tid >> 6) * 4;
        #pragma unroll
        for (int ps = 0; ps < 4; ps++) {
            int d = d4 + ps * 16;
            float4 v = *(const float4*)&Bp[(size_t)(p0 + pp) * 1024 + h * 64 + d];
            Bs[(d + 0) * ABT_BS_STRIDE + pp] = f2tf32(v.x);
            Bs[(d + 1) * ABT_BS_STRIDE + pp] = f2tf32(v.y);
            Bs[(d + 2) * ABT_BS_STRIDE + pp] = f2tf32(v.z);
            Bs[(d + 3) * ABT_BS_STRIDE + pp] = f2tf32(v.w);
        }
    }
    __syncthreads();

    float acc[8][4];
    #pragma unroll
    for (int t = 0; t < 8; t++)
        #pragma unroll
        for (int j = 0; j < 4; j++) acc[t][j] = 0.0f;

    #pragma unroll
    for (int ks = 0; ks < 8; ks++) {
        int kb = ks * 8;
        uint32_t af[2][4], bf[4][2];
        #pragma unroll
        for (int i = 0; i < 2; i++) {
            int r = wm + i * 16 + (lane >> 2);
            int c = kb + (lane & 3);
            af[i][0] = As[r * ABT_AS_STRIDE + c];
            af[i][1] = As[(r + 8) * ABT_AS_STRIDE + c];
            af[i][2] = As[r * ABT_AS_STRIDE + c + 4];
            af[i][3] = As[(r + 8) * ABT_AS_STRIDE + c + 4];
        }
        #pragma unroll
        for (int j = 0; j < 4; j++) {
            int r = kb + (lane & 3);
            int c = wn + j * 8 + (lane >> 2);
            bf[j][0] = Bs[r * ABT_BS_STRIDE + c];
            bf[j][1] = Bs[(r + 4) * ABT_BS_STRIDE + c];
        }
        #pragma unroll
        for (int i = 0; i < 2; i++)
            #pragma unroll
            for (int j = 0; j < 4; j++)
                mma_tf32(acc[i * 4 + j], af[i], bf[j]);
    }

    #pragma unroll
    for (int i = 0; i < 2; i++) {
        #pragma unroll
        for (int j = 0; j < 4; j++) {
            int r = r0 + wm + i * 16 + (lane >> 2);
            int c = p0 + wn + j * 8 + (lane & 3) * 2;
            float2 v0 = {acc[i * 4 + j][0], acc[i * 4 + j][1]};
            *(float2*)&Cp[((size_t)h * (NBATCH * SEQ) + r) * POS2 + c] = v0;
            float2 v1 = {acc[i * 4 + j][2], acc[i * 4 + j][3]};
            *(float2*)&Cp[((size_t)h * (NBATCH * SEQ) + r + 8) * POS2 + c] = v1;
        }
    }
}

// ================= tensor-core flash attention ===============================
// 64(q) x 64(k) tiles, 128 threads (4 warps x 16 q-rows), TF32 mma for S and PV
#define AQS 68   // Qs/Ks/Ps stride (conflict-free mma reads)
#define AVS 72   // Vs stride

__global__ __launch_bounds__(128) void attn_tc_kernel(
    const int* __restrict__ mask, float* __restrict__ out) {
    extern __shared__ uint32_t sm[];
    uint32_t* Qs = sm;                 // [64][68]
    uint32_t* Ks = Qs + 64 * AQS;      // [64][68]
    uint32_t* Vs = Ks + 64 * AQS;      // [64][72]
    uint32_t* Ps = Vs + 64 * AVS;      // [64][68]

    int tid = threadIdx.x;
    int lane = tid & 31, wid = tid >> 5;
    int bh = blockIdx.y;
    int b = bh >> 4, h = bh & 15;
    int q0 = blockIdx.x * 64;
    int wrow = wid * 16;

    // load Q tile (tf32)
    #pragma unroll
    for (int it = 0; it < 8; it++) {
        int idx = tid + it * 128;
        int row = idx >> 4, col = (idx & 15) * 4;
        float4 v = *(const float4*)&g_Q[(size_t)(b * SEQ + q0 + row) * 1024 + h * 64 + col];
        uint32_t* d = &Qs[row * AQS + col];
        d[0] = f2tf32(v.x); d[1] = f2tf32(v.y); d[2] = f2tf32(v.z); d[3] = f2tf32(v.w);
    }

    int r0l = wrow + (lane >> 2);       // local q row (and +8)
    int row0 = q0 + r0l, row1 = row0 + 8;
    const float* c2p0 = &g_c2p[((size_t)h * (NBATCH * SEQ) + b * SEQ + row0) * POS2];
    const float* c2p1 = &g_c2p[((size_t)h * (NBATCH * SEQ) + b * SEQ + row1) * POS2];
    const float* p2cb = &g_p2c[((size_t)h * (NBATCH * SEQ) + b * SEQ) * POS2];
    const int* mrow0 = &mask[((size_t)b * SEQ + row0) * SEQ];
    const int* mrow1 = &mask[((size_t)b * SEQ + row1) * SEQ];

    float m_run0 = -FLT_MAX, m_run1 = -FLT_MAX, l_run0 = 0.0f, l_run1 = 0.0f;
    float O[8][4];
    #pragma unroll
    for (int f = 0; f < 8; f++)
        #pragma unroll
        for (int j = 0; j < 4; j++) O[f][j] = 0.0f;

    const float inv_scale = 0.07216878364870323f; // 1/sqrt(64*3)

    for (int k0 = 0; k0 < SEQ; k0 += 64) {
        __syncthreads();
        // load K,V tiles (tf32)
        #pragma unroll
        for (int it = 0; it < 8; it++) {
            int idx = tid + it * 128;
            int row = idx >> 4, col = (idx & 15) * 4;
            float4 kv = *(const float4*)&g_K[(size_t)(b * SEQ + k0 + row) * 1024 + h * 64 + col];
            uint32_t* dk = &Ks[row * AQS + col];
            dk[0] = f2tf32(kv.x); dk[1] = f2tf32(kv.y); dk[2] = f2tf32(kv.z); dk[3] = f2tf32(kv.w);
            float4 vv = *(const float4*)&g_V[(size_t)(b * SEQ + k0 + row) * 1024 + h * 64 + col];
            uint32_t* dv = &Vs[row * AVS + col];
            dv[0] = f2tf32(vv.x); dv[1] = f2tf32(vv.y); dv[2] = f2tf32(vv.z); dv[3] = f2tf32(vv.w);
        }
        __syncthreads();

        // ---- S = Q K^T
        float sa[8][4];
        #pragma unroll
        for (int f = 0; f < 8; f++)
            #pragma unroll
            for (int j = 0; j < 4; j++) sa[f][j] = 0.0f;

        #pragma unroll
        for (int ks = 0; ks < 8; ks++) {
            int kb = ks * 8;
            uint32_t a[4];
            a[0] = Qs[r0l * AQS + kb + (lane & 3)];
            a[1] = Qs[(r0l + 8) * AQS + kb + (lane & 3)];
            a[2] = Qs[r0l * AQS + kb + 4 + (lane & 3)];
            a[3] = Qs[(r0l + 8) * AQS + kb + 4 + (lane & 3)];
            #pragma unroll
            for (int nf = 0; nf < 8; nf++) {
                int n = nf * 8 + (lane >> 2);
                uint32_t bf[2];
                bf[0] = Ks[n * AQS + kb + (lane & 3)];
                bf[1] = Ks[n * AQS + kb + 4 + (lane & 3)];
                mma_tf32(sa[nf], a, bf);
            }
        }

        // ---- bias + scale + mask
        float s0max = -FLT_MAX, s1max = -FLT_MAX;
        #pragma unroll
        for (int nf = 0; nf < 8; nf++) {
            #pragma unroll
            for (int j = 0; j < 2; j++) {
                int kg = k0 + nf * 8 + 2 * (lane & 3) + j;
                int d0 = row0 - kg + 1023;
                int iC0 = __ldg(&g_idxC[d0]);
                int iP0 = __ldg(&g_idxP[d0]);
                int iC1 = __ldg(&g_idxC[d0 + 8]);
                int iP1 = __ldg(&g_idxP[d0 + 8]);
                float v0 = (sa[nf][j] + __ldg(&c2p0[iC0]) + __ldg(&p2cb[(size_t)kg * POS2 + iP0])) * inv_scale;
                float v1 = (sa[nf][j + 2] + __ldg(&c2p1[iC1]) + __ldg(&p2cb[(size_t)kg * POS2 + iP1])) * inv_scale;
                v0 = mrow0[kg] ? v0 : -FLT_MAX;
                v1 = mrow1[kg] ? v1 : -FLT_MAX;
                sa[nf][j] = v0; sa[nf][j + 2] = v1;
                s0max = fmaxf(s0max, v0); s1max = fmaxf(s1max, v1);
            }
        }

        // ---- online softmax
        s0max = fmaxf(s0max, __shfl_xor_sync(0xffffffffu, s0max, 1));
        s0max = fmaxf(s0max, __shfl_xor_sync(0xffffffffu, s0max, 2));
        s1max = fmaxf(s1max, __shfl_xor_sync(0xffffffffu, s1max, 1));
        s1max = fmaxf(s1max, __shfl_xor_sync(0xffffffffu, s1max, 2));
        float m0n = fmaxf(m_run0, s0max), m1n = fmaxf(m_run1, s1max);
        float a0 = __expf(m_run0 - m0n), a1 = __expf(m_run1 - m1n);
        float psum0 = 0.0f, psum1 = 0.0f;
        #pragma unroll
        for (int nf = 0; nf < 8; nf++) {
            float p00 = __expf(sa[nf][0] - m0n);
            float p01 = __expf(sa[nf][1] - m0n);
            float p10 = __expf(sa[nf][2] - m1n);
            float p11 = __expf(sa[nf][3] - m1n);
            psum0 += p00 + p01; psum1 += p10 + p11;
            int c = nf * 8 + 2 * (lane & 3);
            uint2 w0; w0.x = f2tf32(p00); w0.y = f2tf32(p01);
            *(uint2*)&Ps[r0l * AQS + c] = w0;
            uint2 w1; w1.x = f2tf32(p10); w1.y = f2tf32(p11);
            *(uint2*)&Ps[(r0l + 8) * AQS + c] = w1;
        }
        psum0 += __shfl_xor_sync(0xffffffffu, psum0, 1);
        psum0 += __shfl_xor_sync(0xffffffffu, psum0, 2);
        psum1 += __shfl_xor_sync(0xffffffffu, psum1, 1);
        psum1 += __shfl_xor_sync(0xffffffffu, psum1, 2);
        l_run0 = l_run0 * a0 + psum0;
        l_run1 = l_run1 * a1 + psum1;
        m_run0 = m0n; m_run1 = m1n;
        #pragma unroll
        for (int f = 0; f < 8; f++) {
            O[f][0] *= a0; O[f][1] *= a0; O[f][2] *= a1; O[f][3] *= a1;
        }
        __syncwarp();

        // ---- O += P V   (P rows are warp-private in Ps)
        #pragma unroll
        for (int ks = 0; ks < 8; ks++) {
            int kb = ks * 8;
            uint32_t a[4];
            a[0] = Ps[r0l * AQS + kb + (lane & 3)];
            a[1] = Ps[(r0l + 8) * AQS + kb + (lane & 3)];
            a[2] = Ps[r0l * AQS + kb + 4 + (lane & 3)];
            a[3] = Ps[(r0l + 8) * AQS + kb + 4 + (lane & 3)];
            #pragma unroll
            for (int nf = 0; nf < 8; nf++) {
                int n = nf * 8 + (lane >> 2);
                uint32_t bf[2];
                bf[0] = Vs[(kb + (lane & 3)) * AVS + n];
                bf[1] = Vs[(kb + 4 + (lane & 3)) * AVS + n];
                mma_tf32(O[nf], a, bf);
            }
        }
        __syncwarp();
    }

    // ---- epilogue
    float invl0 = (m_run0 == -FLT_MAX) ? 0.0f : (1.0f / l_run0);
    float invl1 = (m_run1 == -FLT_MAX) ? 0.0f : (1.0f / l_run1);
    #pragma unroll
    for (int nf = 0; nf < 8; nf++) {
        int d = nf * 8 + 2 * (lane & 3);
        float2 o0 = {O[nf][0] * invl0, O[nf][1] * invl0};
        *(float2*)&out[(size_t)(b * SEQ + row0) * 1024 + h * 64 + d] = o0;
        float2 o1 = {O[nf][2] * invl1, O[nf][3] * invl1};
        *(float2*)&out[(size_t)(b * SEQ + row1) * 1024 + h * 64 + d] = o1;
    }
}

// ---------------- launch ----------------------------------------------------
extern "C" void kernel_launch(void* const* d_in, const int* in_sizes, int n_in,
                              void* d_out, int out_size) {
    const float* hidden = (const float*)d_in[0];
    const int*   mask   = (const int*)d_in[1];
    const float* rel    = (const float*)d_in[2];
    const float* Wq     = (const float*)d_in[3];
    const float* bq     = (const float*)d_in[4];
    const float* Wk     = (const float*)d_in[5];
    const float* bk     = (const float*)d_in[6];
    const float* Wv     = (const float*)d_in[7];
    const float* bv     = (const float*)d_in[8];
    float* out = (float*)d_out;

    init_tables_kernel<<<8, 256>>>();

    int smem_qkv = (2 * QKV_ABUF + 2 * QKV_BBUF) * (int)sizeof(uint32_t);
    cudaFuncSetAttribute(gemm_proj_tf32, cudaFuncAttributeMaxDynamicSharedMemorySize, smem_qkv);
    gemm_proj_tf32<<<dim3(8, 20, 3), 256, smem_qkv>>>(
        hidden, rel, Wq, Wk, Wv, bq, bk, bv);

    int smem_abt = (128 * ABT_AS_STRIDE + 64 * ABT_BS_STRIDE) * (int)sizeof(uint32_t);
    cudaFuncSetAttribute(gemm_abT_tf32, cudaFuncAttributeMaxDynamicSharedMemorySize, smem_abt);
    gemm_abT_tf32<<<dim3(8, 16, 32), 256, smem_abt>>>();

    int smem_attn = (3 * 64 * AQS + 64 * AVS) * (int)sizeof(uint32_t);
    cudaFuncSetAttribute(attn_tc_kernel, cudaFuncAttributeMaxDynamicSharedMemorySize, smem_attn);
    attn_tc_kernel<<<dim3(SEQ / 64, NBATCH * NHEAD), 128, smem_attn>>>(mask, out);
}

// round 4
// speedup vs baseline: 2.9941x; 1.2026x over previous
#include <cuda_runtime.h>
#include <math.h>
#include <float.h>
#include <stdint.h>

#define SEQ    1024
#define DMODEL 1024
#define NHEAD  16
#define DHEAD  64
#define NBATCH 2
#define POS2   512

// ---------------- scratch ----------------------------------------------------
__device__ float g_Q[NBATCH * SEQ * DMODEL];
__device__ float g_K[NBATCH * SEQ * DMODEL];
__device__ float g_V[NBATCH * SEQ * DMODEL];
__device__ float g_PQ[POS2 * DMODEL];
__device__ float g_PK[POS2 * DMODEL];
__device__ float g_c2p[NHEAD * NBATCH * SEQ * POS2];
__device__ float g_p2c[NHEAD * NBATCH * SEQ * POS2];
__device__ int2  g_idx2[2047];                         // (idxC, idxP)
__device__ unsigned g_pmask[NBATCH * SEQ * (SEQ / 32)]; // bit-packed mask

// ---------------- helpers ----------------------------------------------------
__device__ __forceinline__ uint32_t f2tf32(float x) {
    uint32_t r;
    asm("cvt.rna.tf32.f32 %0, %1;" : "=r"(r) : "f"(x));
    return r;
}
__device__ __forceinline__ void mma_tf32(float c[4], const uint32_t a[4], const uint32_t b[2]) {
    asm volatile(
        "mma.sync.aligned.m16n8k8.row.col.f32.tf32.tf32.f32 "
        "{%0,%1,%2,%3}, {%4,%5,%6,%7}, {%8,%9}, {%0,%1,%2,%3};"
        : "+f"(c[0]), "+f"(c[1]), "+f"(c[2]), "+f"(c[3])
        : "r"(a[0]), "r"(a[1]), "r"(a[2]), "r"(a[3]), "r"(b[0]), "r"(b[1]));
}

// ---------------- log-bucket tables ------------------------------------------
__device__ __forceinline__ int log_bucket(int rel) {
    const int mid = 128;
    float absp;
    if (rel < mid && rel > -mid) absp = (float)(mid - 1);
    else absp = fabsf((float)rel);
    if (absp <= (float)mid) return rel;
    float lp = ceilf(logf(absp / 128.0f) / 1.3843393291f * 127.0f) + 128.0f;
    float sgn = (rel > 0) ? 1.0f : ((rel < 0) ? -1.0f : 0.0f);
    return (int)(lp * sgn);
}
__global__ void init_tables_kernel() {
    int t = blockIdx.x * blockDim.x + threadIdx.x;
    if (t < 2047) {
        int delta = t - 1023;
        int bC = log_bucket(delta);
        int bP = log_bucket(-delta);
        int2 v;
        v.x = min(max(bC + 256, 0), 511);
        v.y = min(max(-bP + 256, 0), 511);
        g_idx2[t] = v;
    }
}

// ---------------- mask bit-pack ----------------------------------------------
__global__ void pack_mask_kernel(const int* __restrict__ mask) {
    int idx = blockIdx.x * 256 + threadIdx.x;   // over B*S*S elements
    int v = mask[idx];
    unsigned bal = __ballot_sync(0xffffffffu, v != 0);
    if ((threadIdx.x & 31) == 0) g_pmask[idx >> 5] = bal;
}

// ================= TF32 GEMM: projections (QKV + positional merged) ==========
#define QKV_AS_STRIDE 36
#define QKV_BS_STRIDE 136
#define QKV_ABUF (128 * QKV_AS_STRIDE)
#define QKV_BBUF (32 * QKV_BS_STRIDE)

__global__ __launch_bounds__(256) void gemm_proj_tf32(
    const float* __restrict__ hidden, const float* __restrict__ rel,
    const float* __restrict__ Wq, const float* __restrict__ Wk, const float* __restrict__ Wv,
    const float* __restrict__ bq, const float* __restrict__ bk, const float* __restrict__ bv) {

    int z = blockIdx.z;
    int y = blockIdx.y;
    const float* A;
    float* C;
    int m0;
    if (y < 16) {
        A = hidden; m0 = y * 128;
        C = (z == 0) ? g_Q : (z == 1) ? g_K : g_V;
    } else {
        if (z == 2) return;
        A = rel; m0 = (y - 16) * 128;
        C = (z == 0) ? g_PQ : g_PK;
    }
    const float* W = (z == 0) ? Wq : (z == 1) ? Wk : Wv;
    const float* bias = (z == 0) ? bq : (z == 1) ? bk : bv;

    extern __shared__ uint32_t smu[];
    uint32_t* As = smu;
    uint32_t* Bs = smu + 2 * QKV_ABUF;

    int tid = threadIdx.x;
    int lane = tid & 31, wid = tid >> 5;
    int wm = (wid >> 2) * 64, wn = (wid & 3) * 32;
    int n0 = blockIdx.x * 128;

    int arow = tid >> 3, acol = (tid & 7) * 4;
    int brow = tid >> 5, bcol = (tid & 31) * 4;

    float4 ra[4], rb[4];
    float acc[16][4];
    #pragma unroll
    for (int t = 0; t < 16; t++)
        #pragma unroll
        for (int j = 0; j < 4; j++) acc[t][j] = 0.0f;

    #pragma unroll
    for (int p = 0; p < 4; p++) {
        ra[p] = *(const float4*)&A[(size_t)(m0 + arow + p * 32) * 1024 + acol];
        rb[p] = *(const float4*)&W[(size_t)(brow + p * 8) * 1024 + n0 + bcol];
    }
    #pragma unroll
    for (int p = 0; p < 4; p++) {
        uint32_t* d = &As[(arow + p * 32) * QKV_AS_STRIDE + acol];
        d[0] = f2tf32(ra[p].x); d[1] = f2tf32(ra[p].y); d[2] = f2tf32(ra[p].z); d[3] = f2tf32(ra[p].w);
        uint32_t* e = &Bs[(brow + p * 8) * QKV_BS_STRIDE + bcol];
        e[0] = f2tf32(rb[p].x); e[1] = f2tf32(rb[p].y); e[2] = f2tf32(rb[p].z); e[3] = f2tf32(rb[p].w);
    }
    __syncthreads();

    int buf = 0;
    for (int kk = 32; kk <= 1024; kk += 32) {
        if (kk < 1024) {
            #pragma unroll
            for (int p = 0; p < 4; p++) {
                ra[p] = *(const float4*)&A[(size_t)(m0 + arow + p * 32) * 1024 + kk + acol];
                rb[p] = *(const float4*)&W[(size_t)(kk + brow + p * 8) * 1024 + n0 + bcol];
            }
        }
        const uint32_t* Ab = &As[buf * QKV_ABUF];
        const uint32_t* Bb = &Bs[buf * QKV_BBUF];
        #pragma unroll
        for (int ks = 0; ks < 4; ks++) {
            int kb = ks * 8;
            uint32_t af[4][4], bf[4][2];
            #pragma unroll
            for (int i = 0; i < 4; i++) {
                int r = wm + i * 16 + (lane >> 2);
                int c = kb + (lane & 3);
                af[i][0] = Ab[r * QKV_AS_STRIDE + c];
                af[i][1] = Ab[(r + 8) * QKV_AS_STRIDE + c];
                af[i][2] = Ab[r * QKV_AS_STRIDE + c + 4];
                af[i][3] = Ab[(r + 8) * QKV_AS_STRIDE + c + 4];
            }
            #pragma unroll
            for (int j = 0; j < 4; j++) {
                int r = kb + (lane & 3);
                int c = wn + j * 8 + (lane >> 2);
                bf[j][0] = Bb[r * QKV_BS_STRIDE + c];
                bf[j][1] = Bb[(r + 4) * QKV_BS_STRIDE + c];
            }
            #pragma unroll
            for (int i = 0; i < 4; i++)
                #pragma unroll
                for (int j = 0; j < 4; j++)
                    mma_tf32(acc[i * 4 + j], af[i], bf[j]);
        }
        __syncthreads();
        if (kk < 1024) {
            buf ^= 1;
            #pragma unroll
            for (int p = 0; p < 4; p++) {
                uint32_t* d = &As[buf * QKV_ABUF + (arow + p * 32) * QKV_AS_STRIDE + acol];
                d[0] = f2tf32(ra[p].x); d[1] = f2tf32(ra[p].y); d[2] = f2tf32(ra[p].z); d[3] = f2tf32(ra[p].w);
                uint32_t* e = &Bs[buf * QKV_BBUF + (brow + p * 8) * QKV_BS_STRIDE + bcol];
                e[0] = f2tf32(rb[p].x); e[1] = f2tf32(rb[p].y); e[2] = f2tf32(rb[p].z); e[3] = f2tf32(rb[p].w);
            }
            __syncthreads();
        }
    }

    #pragma unroll
    for (int i = 0; i < 4; i++) {
        #pragma unroll
        for (int j = 0; j < 4; j++) {
            int r = m0 + wm + i * 16 + (lane >> 2);
            int c = n0 + wn + j * 8 + (lane & 3) * 2;
            float bx = bias[c], by = bias[c + 1];
            float2 v0 = {acc[i * 4 + j][0] + bx, acc[i * 4 + j][1] + by};
            *(float2*)&C[(size_t)r * 1024 + c] = v0;
            float2 v1 = {acc[i * 4 + j][2] + bx, acc[i * 4 + j][3] + by};
            *(float2*)&C[(size_t)(r + 8) * 1024 + c] = v1;
        }
    }
}

// ============ TF32 per-head A@B^T (c2p_att / p2c_att) ========================
#define ABT_AS_STRIDE 68
#define ABT_BS_STRIDE 136

__global__ __launch_bounds__(256) void gemm_abT_tf32() {
    int z = blockIdx.z;
    int h = z & 15;
    const float* Ap = (z < 16) ? g_Q : g_K;
    const float* Bp = (z < 16) ? g_PK : g_PQ;
    float* Cp = (z < 16) ? g_c2p : g_p2c;

    extern __shared__ uint32_t smu[];
    uint32_t* As = smu;
    uint32_t* Bs = smu + 128 * ABT_AS_STRIDE;

    int tid = threadIdx.x;
    int lane = tid & 31, wid = tid >> 5;
    int wm = (wid >> 1) * 32, wn = (wid & 1) * 32;
    int r0 = blockIdx.y * 128, p0 = blockIdx.x * 64;

    {
        int row = tid >> 4, col = (tid & 15) * 4;
        #pragma unroll
        for (int p = 0; p < 8; p++) {
            float4 v = *(const float4*)&Ap[(size_t)(r0 + row + p * 16) * 1024 + h * 64 + col];
            uint32_t* d = &As[(row + p * 16) * ABT_AS_STRIDE + col];
            d[0] = f2tf32(v.x); d[1] = f2tf32(v.y); d[2] = f2tf32(v.z); d[3] = f2tf32(v.w);
        }
    }
    {
        int pp = tid & 63, d4 = (tid >> 6) * 4;
        #pragma unroll
        for (int ps = 0; ps < 4; ps++) {
            int d = d4 + ps * 16;
            float4 v = *(const float4*)&Bp[(size_t)(p0 + pp) * 1024 + h * 64 + d];
            Bs[(d + 0) * ABT_BS_STRIDE + pp] = f2tf32(v.x);
            Bs[(d + 1) * ABT_BS_STRIDE + pp] = f2tf32(v.y);
            Bs[(d + 2) * ABT_BS_STRIDE + pp] = f2tf32(v.z);
            Bs[(d + 3) * ABT_BS_STRIDE + pp] = f2tf32(v.w);
        }
    }
    __syncthreads();

    float acc[8][4];
    #pragma unroll
    for (int t = 0; t < 8; t++)
        #pragma unroll
        for (int j = 0; j < 4; j++) acc[t][j] = 0.0f;

    #pragma unroll
    for (int ks = 0; ks < 8; ks++) {
        int kb = ks * 8;
        uint32_t af[2][4], bf[4][2];
        #pragma unroll
        for (int i = 0; i < 2; i++) {
            int r = wm + i * 16 + (lane >> 2);
            int c = kb + (lane & 3);
            af[i][0] = As[r * ABT_AS_STRIDE + c];
            af[i][1] = As[(r + 8) * ABT_AS_STRIDE + c];
            af[i][2] = As[r * ABT_AS_STRIDE + c + 4];
            af[i][3] = As[(r + 8) * ABT_AS_STRIDE + c + 4];
        }
        #pragma unroll
        for (int j = 0; j < 4; j++) {
            int r = kb + (lane & 3);
            int c = wn + j * 8 + (lane >> 2);
            bf[j][0] = Bs[r * ABT_BS_STRIDE + c];
            bf[j][1] = Bs[(r + 4) * ABT_BS_STRIDE + c];
        }
        #pragma unroll
        for (int i = 0; i < 2; i++)
            #pragma unroll
            for (int j = 0; j < 4; j++)
                mma_tf32(acc[i * 4 + j], af[i], bf[j]);
    }

    #pragma unroll
    for (int i = 0; i < 2; i++) {
        #pragma unroll
        for (int j = 0; j < 4; j++) {
            int r = r0 + wm + i * 16 + (lane >> 2);
            int c = p0 + wn + j * 8 + (lane & 3) * 2;
            float2 v0 = {acc[i * 4 + j][0], acc[i * 4 + j][1]};
            *(float2*)&Cp[((size_t)h * (NBATCH * SEQ) + r) * POS2 + c] = v0;
            float2 v1 = {acc[i * 4 + j][2], acc[i * 4 + j][3]};
            *(float2*)&Cp[((size_t)h * (NBATCH * SEQ) + r + 8) * POS2 + c] = v1;
        }
    }
}

// ================= tensor-core flash attention (v2) ==========================
// 64(q) x 64(k) tiles, 128 threads; no Ps smem (shfl transpose); 4 CTAs/SM
#define AQS 68
#define AVS 72

__global__ __launch_bounds__(128, 4) void attn_tc_kernel(float* __restrict__ out) {
    extern __shared__ uint32_t sm[];
    uint32_t* Qs = sm;              // [64][68]
    uint32_t* Ks = Qs + 64 * AQS;   // [64][68]
    uint32_t* Vs = Ks + 64 * AQS;   // [64][72]

    int tid = threadIdx.x;
    int lane = tid & 31, wid = tid >> 5;
    int bh = blockIdx.y;
    int b = bh >> 4, h = bh & 15;
    int q0 = blockIdx.x * 64;

    // load Q tile (tf32)
    #pragma unroll
    for (int it = 0; it < 8; it++) {
        int idx = tid + it * 128;
        int row = idx >> 4, col = (idx & 15) * 4;
        float4 v = *(const float4*)&g_Q[(size_t)(b * SEQ + q0 + row) * 1024 + h * 64 + col];
        uint32_t* d = &Qs[row * AQS + col];
        d[0] = f2tf32(v.x); d[1] = f2tf32(v.y); d[2] = f2tf32(v.z); d[3] = f2tf32(v.w);
    }

    int qd = lane & 3, e = qd & 1;
    int srcA = (lane & ~3) | (qd >> 1);
    int srcB = srcA + 2;

    int r0l = wid * 16 + (lane >> 2);
    int row0 = q0 + r0l, row1 = row0 + 8;
    const float* c2p0 = &g_c2p[((size_t)h * (NBATCH * SEQ) + b * SEQ + row0) * POS2];
    const float* c2p1 = &g_c2p[((size_t)h * (NBATCH * SEQ) + b * SEQ + row1) * POS2];
    const float* p2cb = &g_p2c[((size_t)h * (NBATCH * SEQ) + b * SEQ) * POS2];
    const unsigned* pm0 = &g_pmask[(size_t)(b * SEQ + row0) * 32];
    const unsigned* pm1 = &g_pmask[(size_t)(b * SEQ + row1) * 32];

    float m_run0 = -FLT_MAX, m_run1 = -FLT_MAX, l_run0 = 0.0f, l_run1 = 0.0f;
    float O[8][4];
    #pragma unroll
    for (int f = 0; f < 8; f++)
        #pragma unroll
        for (int j = 0; j < 4; j++) O[f][j] = 0.0f;

    const float inv_scale = 0.07216878364870323f; // 1/sqrt(64*3)

    for (int k0 = 0; k0 < SEQ; k0 += 64) {
        __syncthreads();
        #pragma unroll
        for (int it = 0; it < 8; it++) {
            int idx = tid + it * 128;
            int row = idx >> 4, col = (idx & 15) * 4;
            float4 kv = *(const float4*)&g_K[(size_t)(b * SEQ + k0 + row) * 1024 + h * 64 + col];
            float4 vv = *(const float4*)&g_V[(size_t)(b * SEQ + k0 + row) * 1024 + h * 64 + col];
            uint32_t* dk = &Ks[row * AQS + col];
            dk[0] = f2tf32(kv.x); dk[1] = f2tf32(kv.y); dk[2] = f2tf32(kv.z); dk[3] = f2tf32(kv.w);
            uint32_t* dv = &Vs[row * AVS + col];
            dv[0] = f2tf32(vv.x); dv[1] = f2tf32(vv.y); dv[2] = f2tf32(vv.z); dv[3] = f2tf32(vv.w);
        }
        __syncthreads();

        // ---- S = Q K^T
        float sa[8][4];
        #pragma unroll
        for (int f = 0; f < 8; f++)
            #pragma unroll
            for (int j = 0; j < 4; j++) sa[f][j] = 0.0f;

        #pragma unroll
        for (int ks = 0; ks < 8; ks++) {
            int kb = ks * 8;
            uint32_t a[4];
            a[0] = Qs[r0l * AQS + kb + qd];
            a[1] = Qs[(r0l + 8) * AQS + kb + qd];
            a[2] = Qs[r0l * AQS + kb + 4 + qd];
            a[3] = Qs[(r0l + 8) * AQS + kb + 4 + qd];
            #pragma unroll
            for (int nf = 0; nf < 8; nf++) {
                int n = nf * 8 + (lane >> 2);
                uint32_t bf[2];
                bf[0] = Ks[n * AQS + kb + qd];
                bf[1] = Ks[n * AQS + kb + 4 + qd];
                mma_tf32(sa[nf], a, bf);
            }
        }

        // ---- masks (bit-packed)
        unsigned m0a = pm0[k0 >> 5], m0b = pm0[(k0 >> 5) + 1];
        unsigned m1a = pm1[k0 >> 5], m1b = pm1[(k0 >> 5) + 1];

        // ---- bias + scale + mask
        float s0max = -FLT_MAX, s1max = -FLT_MAX;
        #pragma unroll
        for (int nf = 0; nf < 8; nf++) {
            #pragma unroll
            for (int j = 0; j < 2; j++) {
                int kl = nf * 8 + 2 * qd + j;
                int kg = k0 + kl;
                int d0 = row0 - kg + 1023;
                int2 i0 = __ldg(&g_idx2[d0]);
                int2 i1 = __ldg(&g_idx2[d0 + 8]);
                float v0 = (sa[nf][j] + __ldg(&c2p0[i0.x]) + __ldg(&p2cb[(size_t)kg * POS2 + i0.y])) * inv_scale;
                float v1 = (sa[nf][j + 2] + __ldg(&c2p1[i1.x]) + __ldg(&p2cb[(size_t)kg * POS2 + i1.y])) * inv_scale;
                unsigned w0 = (kl & 32) ? m0b : m0a;
                unsigned w1 = (kl & 32) ? m1b : m1a;
                v0 = ((w0 >> (kl & 31)) & 1u) ? v0 : -FLT_MAX;
                v1 = ((w1 >> (kl & 31)) & 1u) ? v1 : -FLT_MAX;
                sa[nf][j] = v0; sa[nf][j + 2] = v1;
                s0max = fmaxf(s0max, v0); s1max = fmaxf(s1max, v1);
            }
        }

        // ---- online softmax (row over quad)
        s0max = fmaxf(s0max, __shfl_xor_sync(0xffffffffu, s0max, 1));
        s0max = fmaxf(s0max, __shfl_xor_sync(0xffffffffu, s0max, 2));
        s1max = fmaxf(s1max, __shfl_xor_sync(0xffffffffu, s1max, 1));
        s1max = fmaxf(s1max, __shfl_xor_sync(0xffffffffu, s1max, 2));
        float m0n = fmaxf(m_run0, s0max), m1n = fmaxf(m_run1, s1max);
        float a0 = __expf(m_run0 - m0n), a1 = __expf(m_run1 - m1n);
        float psum0 = 0.0f, psum1 = 0.0f;
        #pragma unroll
        for (int nf = 0; nf < 8; nf++) {
            sa[nf][0] = __expf(sa[nf][0] - m0n);
            sa[nf][1] = __expf(sa[nf][1] - m0n);
            sa[nf][2] = __expf(sa[nf][2] - m1n);
            sa[nf][3] = __expf(sa[nf][3] - m1n);
            psum0 += sa[nf][0] + sa[nf][1];
            psum1 += sa[nf][2] + sa[nf][3];
        }
        psum0 += __shfl_xor_sync(0xffffffffu, psum0, 1);
        psum0 += __shfl_xor_sync(0xffffffffu, psum0, 2);
        psum1 += __shfl_xor_sync(0xffffffffu, psum1, 1);
        psum1 += __shfl_xor_sync(0xffffffffu, psum1, 2);
        l_run0 = l_run0 * a0 + psum0;
        l_run1 = l_run1 * a1 + psum1;
        m_run0 = m0n; m_run1 = m1n;
        #pragma unroll
        for (int f = 0; f < 8; f++) {
            O[f][0] *= a0; O[f][1] *= a0; O[f][2] *= a1; O[f][3] *= a1;
        }

        // ---- O += P V : transpose P fragments via quad shfl (no smem)
        #pragma unroll
        for (int ks = 0; ks < 8; ks++) {
            float x0 = __shfl_sync(0xffffffffu, sa[ks][0], srcA);
            float x1 = __shfl_sync(0xffffffffu, sa[ks][1], srcA);
            float x2 = __shfl_sync(0xffffffffu, sa[ks][2], srcA);
            float x3 = __shfl_sync(0xffffffffu, sa[ks][3], srcA);
            float y0 = __shfl_sync(0xffffffffu, sa[ks][0], srcB);
            float y1 = __shfl_sync(0xffffffffu, sa[ks][1], srcB);
            float y2 = __shfl_sync(0xffffffffu, sa[ks][2], srcB);
            float y3 = __shfl_sync(0xffffffffu, sa[ks][3], srcB);
            uint32_t a[4];
            a[0] = f2tf32(e ? x1 : x0);
            a[1] = f2tf32(e ? x3 : x2);
            a[2] = f2tf32(e ? y1 : y0);
            a[3] = f2tf32(e ? y3 : y2);
            int kb = ks * 8;
            #pragma unroll
            for (int nf = 0; nf < 8; nf++) {
                int n = nf * 8 + (lane >> 2);
                uint32_t bf[2];
                bf[0] = Vs[(kb + qd) * AVS + n];
                bf[1] = Vs[(kb + 4 + qd) * AVS + n];
                mma_tf32(O[nf], a, bf);
            }
        }
    }

    // ---- epilogue
    float invl0 = (m_run0 == -FLT_MAX) ? 0.0f : (1.0f / l_run0);
    float invl1 = (m_run1 == -FLT_MAX) ? 0.0f : (1.0f / l_run1);
    #pragma unroll
    for (int nf = 0; nf < 8; nf++) {
        int d = nf * 8 + 2 * qd;
        float2 o0 = {O[nf][0] * invl0, O[nf][1] * invl0};
        *(float2*)&out[(size_t)(b * SEQ + row0) * 1024 + h * 64 + d] = o0;
        float2 o1 = {O[nf][2] * invl1, O[nf][3] * invl1};
        *(float2*)&out[(size_t)(b * SEQ + row1) * 1024 + h * 64 + d] = o1;
    }
}

// ---------------- launch ----------------------------------------------------
extern "C" void kernel_launch(void* const* d_in, const int* in_sizes, int n_in,
                              void* d_out, int out_size) {
    const float* hidden = (const float*)d_in[0];
    const int*   mask   = (const int*)d_in[1];
    const float* rel    = (const float*)d_in[2];
    const float* Wq     = (const float*)d_in[3];
    const float* bq     = (const float*)d_in[4];
    const float* Wk     = (const float*)d_in[5];
    const float* bk     = (const float*)d_in[6];
    const float* Wv     = (const float*)d_in[7];
    const float* bv     = (const float*)d_in[8];
    float* out = (float*)d_out;

    init_tables_kernel<<<8, 256>>>();
    pack_mask_kernel<<<NBATCH * SEQ * SEQ / 256, 256>>>(mask);

    int smem_qkv = (2 * QKV_ABUF + 2 * QKV_BBUF) * (int)sizeof(uint32_t);
    cudaFuncSetAttribute(gemm_proj_tf32, cudaFuncAttributeMaxDynamicSharedMemorySize, smem_qkv);
    gemm_proj_tf32<<<dim3(8, 20, 3), 256, smem_qkv>>>(
        hidden, rel, Wq, Wk, Wv, bq, bk, bv);

    int smem_abt = (128 * ABT_AS_STRIDE + 64 * ABT_BS_STRIDE) * (int)sizeof(uint32_t);
    cudaFuncSetAttribute(gemm_abT_tf32, cudaFuncAttributeMaxDynamicSharedMemorySize, smem_abt);
    gemm_abT_tf32<<<dim3(8, 16, 32), 256, smem_abt>>>();

    int smem_attn = (2 * 64 * AQS + 64 * AVS) * (int)sizeof(uint32_t);
    cudaFuncSetAttribute(attn_tc_kernel, cudaFuncAttributeMaxDynamicSharedMemorySize, smem_attn);
    attn_tc_kernel<<<dim3(SEQ / 64, NBATCH * NHEAD), 128, smem_attn>>>(out);
}